// round 17
// baseline (speedup 1.0000x reference)
#include <cuda_runtime.h>
#include <cuda_fp16.h>
#include <math.h>
#include <stdint.h>

// ----------------------------------------------------------------------------
// GATv2 Transformer. GEMMs: fp16 mma.sync, all operands fp16, 3-deep cp.async
// pipeline over a linearized persistent work queue (MODE 3: 2-stage + fused
// LN epilogue). Edge: CSR + dual-state online softmax (fp32 xlr).
// ----------------------------------------------------------------------------

#define MAXN 50000
#define MAXE 800000
#define DIM 128
#define HD 256
#define MLPD 512
#define LWORDS 114688
#define PERSIST_BLOCKS 296     // 148 SMs x 2 CTAs

// ------------------------- scratch (device globals) -------------------------
__device__ __align__(256) float    g_xlr [(size_t)MAXN * 512];
__device__ __align__(256) uint32_t g_h   [(size_t)MAXN * (DIM/2)];
__device__ __align__(256) uint32_t g_go  [(size_t)MAXN * (HD/2)];
__device__ __align__(256) uint32_t g_mid [(size_t)MAXN * (MLPD/2)];
__device__ __align__(256) uint32_t g_wb[2 * LWORDS];
__device__ __align__(256) float    g_blr[2 * 512];
// CSR
__device__ __align__(256) int g_src[MAXE];
__device__ __align__(256) int g_dst[MAXE];
__device__ __align__(256) int g_esrc[MAXE];
__device__ __align__(256) int g_deg[MAXN];
__device__ __align__(256) int g_off[MAXN + 1];
__device__ __align__(256) int g_pos[MAXN];
__device__ __align__(256) int g_bsum[64];
__device__ int g_is64;

// ------------------------- helpers -------------------------
__device__ __forceinline__ uint32_t pack_h(float x, float y) {
    return ((uint32_t)__half_as_ushort(__float2half_rn(y)) << 16)
         | (uint32_t)__half_as_ushort(__float2half_rn(x));
}
__device__ __forceinline__ float fast_gelu(float u) {
    float z2 = 1.5957691216057308f * (u + 0.044715f * u * u * u);
    return u * __fdividef(1.0f, 1.0f + __expf(-z2));
}

// ------------------- detect (block 0) + clear deg (all) ----------------------
__global__ void detclr_kernel(const void* edges, int E, int N) {
    int i = blockIdx.x * blockDim.x + threadIdx.x;
    if (i < N) g_deg[i] = 0;
    if (blockIdx.x == 0) {
        __shared__ int bad;
        if (threadIdx.x == 0) bad = 0;
        __syncthreads();
        const long long* p = (const long long*)edges;
        int n = E < 2048 ? E : 2048;
        for (int k = threadIdx.x; k < n; k += blockDim.x) {
            long long v = p[k];
            if (v < 0 || v >= (long long)N) atomicOr(&bad, 1);
        }
        __syncthreads();
        if (threadIdx.x == 0) g_is64 = bad ? 0 : 1;
    }
}

__global__ void decode_hist_kernel(const void* edges, int E) {
    int i = blockIdx.x * blockDim.x + threadIdx.x;
    if (i >= E) return;
    int s, d;
    if (g_is64) {
        const long long* p = (const long long*)edges;
        s = (int)p[i];
        d = (int)p[(size_t)E + i];
    } else {
        const int* p = (const int*)edges;
        s = p[i];
        d = p[(size_t)E + i];
    }
    g_src[i] = s;
    g_dst[i] = d;
    atomicAdd(&g_deg[d], 1);
}

// ---- scan phase A: per-1024-chunk inclusive scan + chunk totals ----
__global__ void scanA_kernel(int N) {
    int t = threadIdx.x;
    int i = blockIdx.x * 1024 + t;
    int lane = t & 31, w = t >> 5;
    int v = (i < N) ? g_deg[i] : 0;
    int s = v;
    #pragma unroll
    for (int o = 1; o < 32; o <<= 1) {
        int u = __shfl_up_sync(0xffffffffu, s, o);
        if (lane >= o) s += u;
    }
    __shared__ int wt[32];
    if (lane == 31) wt[w] = s;
    __syncthreads();
    if (w == 0) {
        int x = wt[lane];
        #pragma unroll
        for (int o = 1; o < 32; o <<= 1) {
            int u = __shfl_up_sync(0xffffffffu, x, o);
            if (lane >= o) x += u;
        }
        wt[lane] = x;
    }
    __syncthreads();
    if (w) s += wt[w - 1];
    if (i < N) g_off[i + 1] = s;
    if (t == 1023) g_bsum[blockIdx.x] = s;
}

// ---- scan phase C: each 256-block derives its chunk prefix, finalizes -------
__global__ void scanC_kernel(int N) {
    __shared__ int boff_s;
    int b = (blockIdx.x * 256) >> 10;    // 256-aligned => single chunk per block
    if (threadIdx.x < 32) {
        int acc = 0;
        for (int k = threadIdx.x; k < b; k += 32) acc += g_bsum[k];
        #pragma unroll
        for (int o = 16; o; o >>= 1) acc += __shfl_xor_sync(0xffffffffu, acc, o);
        if (threadIdx.x == 0) boff_s = acc;
    }
    __syncthreads();
    int i = blockIdx.x * 256 + threadIdx.x;
    if (i == 0) g_off[0] = 0;
    if (i >= N) return;
    int inc = g_off[i + 1] + boff_s;
    g_off[i + 1] = inc;
    g_pos[i] = inc - g_deg[i];
}

__global__ void scatter_kernel(int E) {
    int i = blockIdx.x * blockDim.x + threadIdx.x;
    if (i >= E) return;
    int p = atomicAdd(&g_pos[g_dst[i]], 1);
    g_esrc[p] = g_src[i];
}

// ---------------- fused weight convert + bias concat -------------------------
__global__ void wconv_all_kernel(const float* __restrict__ Wl, const float* __restrict__ Wr,
                                 const float* __restrict__ pj, const float* __restrict__ W1,
                                 const float* __restrict__ W2,
                                 const float* __restrict__ bl, const float* __restrict__ br) {
    int idx = blockIdx.x * blockDim.x + threadIdx.x;
    if (idx < 1024) {
        int layer = idx >> 9, j = idx & 511;
        float v = (j < 256) ? bl[layer * HD + j] : br[layer * HD + j - 256];
        g_blr[layer * 512 + j] = v;
    }
    if (idx >= 2 * LWORDS) return;
    int layer = idx / LWORDS;
    int r = idx - layer * LWORDS;
    const float* W; int K, N;
    if (r < 16384)      { W = Wl + (size_t)layer * 32768; K = 128; N = 256; }
    else if (r < 32768) { W = Wr + (size_t)layer * 32768; r -= 16384; K = 128; N = 256; }
    else if (r < 49152) { W = pj + (size_t)layer * 32768; r -= 32768; K = 256; N = 128; }
    else if (r < 81920) { W = W1 + (size_t)layer * 65536; r -= 49152; K = 128; N = 512; }
    else                { W = W2 + (size_t)layer * 65536; r -= 81920; K = 512; N = 128; }
    int kw = K >> 1;
    int n = r / kw, kp = r - n * kw;
    float x = W[(size_t)(2 * kp) * N + n];
    float y = W[(size_t)(2 * kp + 1) * N + n];
    g_wb[idx] = pack_h(x, y);
}

// ------------------------- standalone layernorm ------------------------------
__global__ void ln_kernel(const float* __restrict__ x, const float* __restrict__ g,
                          const float* __restrict__ b,
                          uint32_t* __restrict__ oh, int N) {
    int row = (blockIdx.x * blockDim.x + threadIdx.x) >> 5;
    int lane = threadIdx.x & 31;
    if (row >= N) return;
    const float4* xr = (const float4*)x + (size_t)row * 32;
    float4 v = xr[lane];
    float s  = v.x + v.y + v.z + v.w;
    float sq = v.x*v.x + v.y*v.y + v.z*v.z + v.w*v.w;
    #pragma unroll
    for (int o = 16; o; o >>= 1) {
        s  += __shfl_xor_sync(0xffffffffu, s,  o);
        sq += __shfl_xor_sync(0xffffffffu, sq, o);
    }
    float m   = s * (1.0f / 128.0f);
    float var = sq * (1.0f / 128.0f) - m * m;
    float inv = rsqrtf(var + 1e-5f);
    float4 gg = ((const float4*)g)[lane];
    float4 bb = ((const float4*)b)[lane];
    float o0 = (v.x - m) * inv * gg.x + bb.x;
    float o1 = (v.y - m) * inv * gg.y + bb.y;
    float o2 = (v.z - m) * inv * gg.z + bb.z;
    float o3 = (v.w - m) * inv * gg.w + bb.w;
    size_t base = (size_t)row * 64 + lane * 2;
    oh[base]     = pack_h(o0, o1);
    oh[base + 1] = pack_h(o2, o3);
}

// ------------------------- tensor-core GEMM --------------------------------
__device__ __forceinline__ void mma16816(float* c, const uint32_t* a, const uint32_t* b) {
    asm volatile(
        "mma.sync.aligned.m16n8k16.row.col.f32.f16.f16.f32 "
        "{%0,%1,%2,%3}, {%4,%5,%6,%7}, {%8,%9}, {%0,%1,%2,%3};"
        : "+f"(c[0]), "+f"(c[1]), "+f"(c[2]), "+f"(c[3])
        : "r"(a[0]), "r"(a[1]), "r"(a[2]), "r"(a[3]), "r"(b[0]), "r"(b[1]));
}

__device__ __forceinline__ void cpa16(uint32_t dst, const void* src, int bytes) {
    asm volatile("cp.async.cg.shared.global [%0], [%1], 16, %2;\n"
                 :: "r"(dst), "l"(src), "r"(bytes));
}

__device__ __forceinline__ int swz(int row, int kp) {
    return (row << 4) | (((kp >> 2) ^ ((row >> 1) & 3)) << 2) | (kp & 3);
}

#define TILE_WORDS 2048
#define BUF_WORDS  (2 * TILE_WORDS)          // A, B per stage (16 KB)
#define GEMM_SMEM  (3 * BUF_WORDS * 4)       // 48 KB (3-stage, modes 0/1/2)
#define GEMM_SMEM3 65536                     // MODE 3: 2 stages + 64 KB rowbuf

// MODE 0: store fp32; 1: accumulate fp32; 2: GELU -> fp16 out;
// MODE 3: accumulate + fused LayerNorm -> writes x (C) and fp16 h (N==128)
template<int MODE>
__global__ __launch_bounds__(256, 2)
void gemm_kernel(const uint32_t* __restrict__ A_g,
                 const uint32_t* __restrict__ Bh_g,
                 const float* __restrict__ bias, float* __restrict__ C,
                 uint32_t* __restrict__ Ch,
                 const float* __restrict__ lng, const float* __restrict__ lnb,
                 int M, int K, int N) {
    extern __shared__ uint32_t sm[];

    const int tid  = threadIdx.x;
    const int lane = tid & 31;
    const int wid  = tid >> 5;
    const int warp_m = wid & 3;
    const int warp_n = wid >> 2;
    const int g  = lane >> 2;
    const int tg = lane & 3;
    const int kw = K >> 1;
    const int nk = K >> 5;
    const int nx = N >> 7;
    const int ntiles = nx * ((M + 127) >> 7);

    const uint32_t sbase = (uint32_t)__cvta_generic_to_shared(sm);

    auto issue = [&](int t, int kt, int b) {
        const int n0_ = (t % nx) * 128;
        const int m0_ = (t / nx) * 128;
        uint32_t bufb = sbase + (uint32_t)(b * BUF_WORDS) * 4;
        #pragma unroll
        for (int q = 0; q < 2; q++) {
            int chunk = tid + q * 256;
            int row = chunk >> 2, c = chunk & 3;
            int dstw = (row << 4) | ((c ^ ((row >> 1) & 3)) << 2);
            int asz = (m0_ + row < M) ? 16 : 0;
            const uint32_t* asrc = A_g  + (size_t)(m0_ + row) * kw + kt * 16 + c * 4;
            const uint32_t* bsrc = Bh_g + (size_t)(n0_ + row) * kw + kt * 16 + c * 4;
            cpa16(bufb + (uint32_t)dstw * 4,                 asrc, asz);
            cpa16(bufb + (uint32_t)(TILE_WORDS + dstw) * 4,  bsrc, 16);
        }
        asm volatile("cp.async.commit_group;\n");
    };

    float acc[2][8][4];

    auto compute_stage = [&](int buf) {
        const uint32_t* Ah = sm + buf * BUF_WORDS;
        const uint32_t* Bh = Ah + TILE_WORDS;
        #pragma unroll
        for (int ks = 0; ks < 2; ks++) {
            const int kb = ks * 4;
            uint32_t ah[2][4];
            #pragma unroll
            for (int mt = 0; mt < 2; mt++) {
                int r0 = warp_m * 32 + mt * 16;
                ah[mt][0] = Ah[swz(r0 + g,     kb + tg)];
                ah[mt][1] = Ah[swz(r0 + g + 8, kb + tg)];
                ah[mt][2] = Ah[swz(r0 + g,     kb + tg + 8)];
                ah[mt][3] = Ah[swz(r0 + g + 8, kb + tg + 8)];
            }
            #pragma unroll
            for (int nt = 0; nt < 8; nt++) {
                int col = warp_n * 64 + nt * 8 + g;
                uint32_t bh[2];
                bh[0] = Bh[swz(col, kb + tg)];
                bh[1] = Bh[swz(col, kb + tg + 8)];
                #pragma unroll
                for (int mt = 0; mt < 2; mt++)
                    mma16816(acc[mt][nt], ah[mt], bh);
            }
        }
    };

    auto epilogue = [&](int m0, int n0, float* rowbuf) {
        #pragma unroll
        for (int mt = 0; mt < 2; mt++) {
            int rloc = warp_m * 32 + mt * 16 + (lane >> 2);
            int row = m0 + rloc;
            #pragma unroll
            for (int nt = 0; nt < 8; nt++) {
                int col = n0 + warp_n * 64 + nt * 8 + (lane & 3) * 2;
                float2 bb = *(const float2*)(bias + col);
                #pragma unroll
                for (int half = 0; half < 2; half++) {
                    int r = row + half * 8;
                    if (r >= M) continue;
                    float v0 = acc[mt][nt][2 * half]     + bb.x;
                    float v1 = acc[mt][nt][2 * half + 1] + bb.y;
                    if (MODE == 2) {
                        v0 = fast_gelu(v0);
                        v1 = fast_gelu(v1);
                        Ch[(size_t)r * (N >> 1) + (col >> 1)] = pack_h(v0, v1);
                    } else if (MODE == 3) {
                        float2 old = *(float2*)(C + (size_t)r * N + col);
                        rowbuf[(rloc + half * 8) * 128 + (col - n0)]     = v0 + old.x;
                        rowbuf[(rloc + half * 8) * 128 + (col - n0) + 1] = v1 + old.y;
                    } else {
                        float2* dst = (float2*)(C + (size_t)r * N + col);
                        if (MODE == 1) {
                            float2 old = *dst;
                            v0 += old.x; v1 += old.y;
                        }
                        *dst = make_float2(v0, v1);
                    }
                }
            }
        }
    };

    if (MODE != 3) {
        // -------- linearized 3-deep pipeline --------
        const int total = (blockIdx.x < ntiles)
            ? ((ntiles - blockIdx.x + gridDim.x - 1) / gridDim.x) * nk : 0;
        auto wtile = [&](int q) { return blockIdx.x + (q / nk) * gridDim.x; };

        if (total > 0) issue(wtile(0), 0, 0);
        if (total > 1) issue(wtile(1), 1 % nk, 1);

        for (int q = 0; q < total; q++) {
            int kt = q % nk;
            int tile = wtile(q);
            if (kt == 0) {
                #pragma unroll
                for (int i = 0; i < 2; i++)
                    #pragma unroll
                    for (int j = 0; j < 8; j++)
                        #pragma unroll
                        for (int r = 0; r < 4; r++) acc[i][j][r] = 0.0f;
            }
            int qn = q + 2;
            if (qn < total) issue(wtile(qn), qn % nk, qn % 3);
            int rem = total - q - 1; if (rem > 2) rem = 2;
            if (rem == 2)      { asm volatile("cp.async.wait_group 2;\n"); }
            else if (rem == 1) { asm volatile("cp.async.wait_group 1;\n"); }
            else               { asm volatile("cp.async.wait_group 0;\n"); }
            __syncthreads();
            compute_stage(q % 3);
            __syncthreads();
            if (kt == nk - 1)
                epilogue((tile / nx) * 128, (tile % nx) * 128, nullptr);
        }
    } else {
        // -------- 2-stage, LN rowbuf epilogue, post-epilogue seed --------
        if (blockIdx.x < ntiles) issue(blockIdx.x, 0, 0);
        for (int tile = blockIdx.x; tile < ntiles; tile += gridDim.x) {
            const int n0 = (tile % nx) * 128;
            const int m0 = (tile / nx) * 128;
            #pragma unroll
            for (int i = 0; i < 2; i++)
                #pragma unroll
                for (int j = 0; j < 8; j++)
                    #pragma unroll
                    for (int r = 0; r < 4; r++) acc[i][j][r] = 0.0f;

            for (int kt = 0; kt < nk; kt++) {
                if (kt + 1 < nk) {
                    issue(tile, kt + 1, (kt + 1) & 1);
                    asm volatile("cp.async.wait_group 1;\n");
                } else {
                    asm volatile("cp.async.wait_group 0;\n");
                }
                __syncthreads();
                compute_stage(kt & 1);
                __syncthreads();
            }

            float* rowbuf = (float*)sm;
            epilogue(m0, n0, rowbuf);
            __syncthreads();
            float4 gg = ((const float4*)lng)[lane];
            float4 bb2 = ((const float4*)lnb)[lane];
            for (int rr = wid * 16; rr < wid * 16 + 16; rr++) {
                int r = m0 + rr;
                if (r >= M) break;
                float4 v = ((const float4*)(rowbuf + rr * 128))[lane];
                float s  = v.x + v.y + v.z + v.w;
                float sq = v.x*v.x + v.y*v.y + v.z*v.z + v.w*v.w;
                #pragma unroll
                for (int o = 16; o; o >>= 1) {
                    s  += __shfl_xor_sync(0xffffffffu, s,  o);
                    sq += __shfl_xor_sync(0xffffffffu, sq, o);
                }
                float m   = s * (1.0f / 128.0f);
                float var = sq * (1.0f / 128.0f) - m * m;
                float inv = rsqrtf(var + 1e-5f);
                ((float4*)(C + (size_t)r * 128))[lane] = v;
                float o0 = (v.x - m) * inv * gg.x + bb2.x;
                float o1 = (v.y - m) * inv * gg.y + bb2.y;
                float o2 = (v.z - m) * inv * gg.z + bb2.z;
                float o3 = (v.w - m) * inv * gg.w + bb2.w;
                size_t base = (size_t)r * 64 + lane * 2;
                Ch[base]     = pack_h(o0, o1);
                Ch[base + 1] = pack_h(o2, o3);
            }
            __syncthreads();
            if (tile + gridDim.x < ntiles)
                issue(tile + gridDim.x, 0, 0);
        }
    }
}

// ------------------- fused GATv2 node kernel (warp per dst) ------------------
__global__ void gat_node_kernel(const float* __restrict__ xlr,
                                const float* __restrict__ att,
                                const float* __restrict__ gat_b,
                                uint32_t* __restrict__ go, int N) {
    int node = (blockIdx.x * blockDim.x + threadIdx.x) >> 5;
    int lane = threadIdx.x & 31;
    if (node >= N) return;

    const float4* base = (const float4*)xlr;
    float4 r0 = base[(size_t)node * 128 + 64 + lane];
    float4 r1 = base[(size_t)node * 128 + 96 + lane];
    float4 a0 = ((const float4*)att)[lane];
    float4 a1 = ((const float4*)att)[32 + lane];

    float mA0 = -1e30f, mA1 = -1e30f, dA0 = 0.f, dA1 = 0.f;
    float mB0 = -1e30f, mB1 = -1e30f, dB0 = 0.f, dB1 = 0.f;
    float4 aA0 = make_float4(0.f,0.f,0.f,0.f), aA1 = make_float4(0.f,0.f,0.f,0.f);
    float4 aB0 = make_float4(0.f,0.f,0.f,0.f), aB1 = make_float4(0.f,0.f,0.f,0.f);

    int beg = g_off[node], end = g_off[node + 1];

    auto process = [&](int s, float& m0, float& m1, float& d0, float& d1,
                       float4& acc0, float4& acc1) {
        float4 l0 = base[(size_t)s * 128 + lane];
        float4 l1 = base[(size_t)s * 128 + 32 + lane];
        float4 e0, e1;
        e0.x = l0.x + r0.x; e0.x = e0.x > 0.f ? e0.x : 0.2f * e0.x;
        e0.y = l0.y + r0.y; e0.y = e0.y > 0.f ? e0.y : 0.2f * e0.y;
        e0.z = l0.z + r0.z; e0.z = e0.z > 0.f ? e0.z : 0.2f * e0.z;
        e0.w = l0.w + r0.w; e0.w = e0.w > 0.f ? e0.w : 0.2f * e0.w;
        e1.x = l1.x + r1.x; e1.x = e1.x > 0.f ? e1.x : 0.2f * e1.x;
        e1.y = l1.y + r1.y; e1.y = e1.y > 0.f ? e1.y : 0.2f * e1.y;
        e1.z = l1.z + r1.z; e1.z = e1.z > 0.f ? e1.z : 0.2f * e1.z;
        e1.w = l1.w + r1.w; e1.w = e1.w > 0.f ? e1.w : 0.2f * e1.w;
        float p0 = e0.x * a0.x + e0.y * a0.y + e0.z * a0.z + e0.w * a0.w;
        float p1 = e1.x * a1.x + e1.y * a1.y + e1.z * a1.z + e1.w * a1.w;
        #pragma unroll
        for (int o = 16; o; o >>= 1) {
            p0 += __shfl_xor_sync(0xffffffffu, p0, o);
            p1 += __shfl_xor_sync(0xffffffffu, p1, o);
        }
        float nm0 = fmaxf(m0, p0);
        float f0 = __expf(m0 - nm0);
        float w0 = __expf(p0 - nm0);
        m0 = nm0;
        d0 = d0 * f0 + w0;
        acc0.x = acc0.x * f0 + w0 * l0.x;
        acc0.y = acc0.y * f0 + w0 * l0.y;
        acc0.z = acc0.z * f0 + w0 * l0.z;
        acc0.w = acc0.w * f0 + w0 * l0.w;
        float nm1 = fmaxf(m1, p1);
        float f1 = __expf(m1 - nm1);
        float w1 = __expf(p1 - nm1);
        m1 = nm1;
        d1 = d1 * f1 + w1;
        acc1.x = acc1.x * f1 + w1 * l1.x;
        acc1.y = acc1.y * f1 + w1 * l1.y;
        acc1.z = acc1.z * f1 + w1 * l1.z;
        acc1.w = acc1.w * f1 + w1 * l1.w;
    };

    int i = beg;
    for (; i + 1 < end; i += 2) {
        int sA = g_esrc[i];
        int sB = g_esrc[i + 1];
        process(sA, mA0, mA1, dA0, dA1, aA0, aA1);
        process(sB, mB0, mB1, dB0, dB1, aB0, aB1);
    }
    if (i < end) process(g_esrc[i], mA0, mA1, dA0, dA1, aA0, aA1);

    {
        float m = fmaxf(mA0, mB0);
        float fA = __expf(mA0 - m), fB = __expf(mB0 - m);
        dA0 = dA0 * fA + dB0 * fB;
        aA0.x = aA0.x * fA + aB0.x * fB;
        aA0.y = aA0.y * fA + aB0.y * fB;
        aA0.z = aA0.z * fA + aB0.z * fB;
        aA0.w = aA0.w * fA + aB0.w * fB;
        m = fmaxf(mA1, mB1);
        fA = __expf(mA1 - m); fB = __expf(mB1 - m);
        dA1 = dA1 * fA + dB1 * fB;
        aA1.x = aA1.x * fA + aB1.x * fB;
        aA1.y = aA1.y * fA + aB1.y * fB;
        aA1.z = aA1.z * fA + aB1.z * fB;
        aA1.w = aA1.w * fA + aB1.w * fB;
    }

    float inv0 = 1.0f / (dA0 + 1e-16f);
    float inv1 = 1.0f / (dA1 + 1e-16f);
    const float4* gb4 = (const float4*)gat_b;
    float4 b0 = gb4[lane];
    float4 b1 = gb4[32 + lane];
    float o0 = aA0.x * inv0 + b0.x, o1 = aA0.y * inv0 + b0.y;
    float o2 = aA0.z * inv0 + b0.z, o3 = aA0.w * inv0 + b0.w;
    float o4 = aA1.x * inv1 + b1.x, o5 = aA1.y * inv1 + b1.y;
    float o6 = aA1.z * inv1 + b1.z, o7 = aA1.w * inv1 + b1.w;

    size_t rb = (size_t)node * 128;
    go[rb + lane * 2]          = pack_h(o0, o1);
    go[rb + lane * 2 + 1]      = pack_h(o2, o3);
    go[rb + 64 + lane * 2]     = pack_h(o4, o5);
    go[rb + 64 + lane * 2 + 1] = pack_h(o6, o7);
}

// ------------------------- launch --------------------------------------------
static inline int pgrid(int ntiles) { return ntiles < PERSIST_BLOCKS ? ntiles : PERSIST_BLOCKS; }

extern "C" void kernel_launch(void* const* d_in, const int* in_sizes, int n_in,
                              void* d_out, int out_size) {
    const float* x_in   = (const float*)d_in[0];
    const void*  edges  = d_in[1];
    const float* ln1_g  = (const float*)d_in[2];
    const float* ln1_b  = (const float*)d_in[3];
    const float* Wl     = (const float*)d_in[4];
    const float* bl     = (const float*)d_in[5];
    const float* Wr     = (const float*)d_in[6];
    const float* br     = (const float*)d_in[7];
    const float* att    = (const float*)d_in[8];
    const float* gat_b  = (const float*)d_in[9];
    const float* projW  = (const float*)d_in[10];
    const float* projb  = (const float*)d_in[11];
    const float* ln2_g  = (const float*)d_in[12];
    const float* ln2_b  = (const float*)d_in[13];
    const float* W1     = (const float*)d_in[14];
    const float* b1     = (const float*)d_in[15];
    const float* W2     = (const float*)d_in[16];
    const float* b2     = (const float*)d_in[17];

    const int N = in_sizes[0] / DIM;
    const int E = in_sizes[1] / 2;
    float* x = (float*)d_out;

    cudaFuncSetAttribute(gemm_kernel<0>, cudaFuncAttributeMaxDynamicSharedMemorySize, GEMM_SMEM);
    cudaFuncSetAttribute(gemm_kernel<1>, cudaFuncAttributeMaxDynamicSharedMemorySize, GEMM_SMEM);
    cudaFuncSetAttribute(gemm_kernel<2>, cudaFuncAttributeMaxDynamicSharedMemorySize, GEMM_SMEM);
    cudaFuncSetAttribute(gemm_kernel<3>, cudaFuncAttributeMaxDynamicSharedMemorySize, GEMM_SMEM3);

    void *p_xlr, *p_h, *p_go, *p_mid, *p_wb, *p_blr;
    cudaGetSymbolAddress(&p_xlr, g_xlr);
    cudaGetSymbolAddress(&p_h, g_h);
    cudaGetSymbolAddress(&p_go, g_go);
    cudaGetSymbolAddress(&p_mid, g_mid);
    cudaGetSymbolAddress(&p_wb, g_wb);
    cudaGetSymbolAddress(&p_blr, g_blr);
    float* xlr = (float*)p_xlr;
    uint32_t* h   = (uint32_t*)p_h;
    uint32_t* go  = (uint32_t*)p_go;
    uint32_t* mid = (uint32_t*)p_mid;
    uint32_t* wb  = (uint32_t*)p_wb;

    cudaMemcpyAsync(x, x_in, (size_t)N * DIM * sizeof(float), cudaMemcpyDeviceToDevice);

    const int nb = (N + 1023) / 1024;
    detclr_kernel<<<(N + 255) / 256, 256>>>(edges, E, N);
    decode_hist_kernel<<<(E + 255) / 256, 256>>>(edges, E);
    scanA_kernel<<<nb, 1024>>>(N);
    scanC_kernel<<<(N + 255) / 256, 256>>>(N);
    scatter_kernel<<<(E + 255) / 256, 256>>>(E);

    wconv_all_kernel<<<(2 * LWORDS + 255) / 256, 256>>>(Wl, Wr, projW, W1, W2, bl, br);

    const int ln_blocks = (N + 7) / 8;
    const int mtiles = (N + 127) / 128;

    ln_kernel<<<ln_blocks, 256>>>(x, ln1_g, ln1_b, h, N);

    for (int l = 0; l < 2; l++) {
        size_t off = (size_t)l * LWORDS;
        const uint32_t* wlr = wb + off;
        const uint32_t* pj  = wb + off + 32768;
        const uint32_t* w1  = wb + off + 49152;
        const uint32_t* w2  = wb + off + 81920;
        const float* at_l = att + (size_t)l * HD;
        const float* gb_l = gat_b + (size_t)l * HD;
        const float* pb_l = projb + (size_t)l * DIM;
        const float* b1_l = b1 + (size_t)l * MLPD;
        const float* b2_l = b2 + (size_t)l * DIM;

        void* p_blr_f; cudaGetSymbolAddress(&p_blr_f, g_blr);
        float* blr = (float*)p_blr_f;

        // xlr = h @ [Wl|Wr] + blr (fp32 out)
        gemm_kernel<0><<<pgrid(4 * mtiles), 256, GEMM_SMEM>>>(
            h, wlr, blr + (size_t)l * 512, xlr, nullptr,
            nullptr, nullptr, N, DIM, 512);
        // fused GATv2 -> gout fp16
        gat_node_kernel<<<(N + 15) / 16, 512>>>(xlr, at_l, gb_l, go, N);
        // x += gout @ proj + pb; fused LN2 -> h (fp16)
        gemm_kernel<3><<<pgrid(mtiles), 256, GEMM_SMEM3>>>(
            go, pj, pb_l, x, h,
            ln2_g + (size_t)l * DIM, ln2_b + (size_t)l * DIM, N, HD, DIM);
        // mid = gelu(h @ W1 + b1) -> fp16
        gemm_kernel<2><<<pgrid(4 * mtiles), 256, GEMM_SMEM>>>(
            h, w1, b1_l, nullptr, mid,
            nullptr, nullptr, N, DIM, MLPD);
        // x += mid @ W2 + b2; fused LN1 of next layer
        if (l == 0) {
            gemm_kernel<3><<<pgrid(mtiles), 256, GEMM_SMEM3>>>(
                mid, w2, b2_l, x, h,
                ln1_g + DIM, ln1_b + DIM, N, MLPD, DIM);
        } else {
            gemm_kernel<1><<<pgrid(mtiles), 256, GEMM_SMEM>>>(
                mid, w2, b2_l, x, nullptr,
                nullptr, nullptr, N, MLPD, DIM);
        }
    }
}